// round 3
// baseline (speedup 1.0000x reference)
#include <cuda_runtime.h>
#include <math.h>

#define NN 63
#define NP (NN*NN)          // 3969
#define NP64 4032
#define BATCH 256
#define KS 7
#define ML 3

// ---------------- device scratch ----------------
__device__ float g_cosT[33*64];
__device__ float g_sinT[33*64];
__device__ float g_w1[BATCH*147];
__device__ float g_w2[BATCH*147];
__device__ float g_a1[BATCH*25*32];     // [b][pix][ch]
__device__ float g_a2[BATCH*81*32];
__device__ float g_a3[BATCH*289*32];
__device__ float g_a4[BATCH*1089*32];
__device__ float g_h [BATCH*2*NP];      // channel-major [b][2][63*63] raw
__device__ float g_blocksum[BATCH];

__device__ __forceinline__ float gelu_exact(float v) {
    return v * 0.5f * (1.0f + erff(v * 0.70710678118654752f));
}

// ---------------- twiddle init (rows 0..32 only, col 63 zero-pad) -------------
__global__ void init_tw_kernel() {
    int idx = blockIdx.x * blockDim.x + threadIdx.x;
    if (idx < 33*64) {
        int k = idx >> 6, n = idx & 63;
        if (n < 63) {
            float ang = 6.28318530717958647692f * (float)((k * n) % NN) / 63.0f;
            g_cosT[idx] = cosf(ang);
            g_sinT[idx] = sinf(ang);
        } else {
            g_cosT[idx] = 0.f; g_sinT[idx] = 0.f;
        }
    }
}

// ---------------- hypernet ----------------
__global__ void hyper_kernel(const float* __restrict__ kA,
                             const float* __restrict__ w1a, const float* __restrict__ b1a,
                             const float* __restrict__ w2a, const float* __restrict__ b2a,
                             const float* __restrict__ w1b, const float* __restrict__ b1b,
                             const float* __restrict__ w2b, const float* __restrict__ b2b) {
    int b = blockIdx.x;
    __shared__ float a[9], h1[100], h2[100];
    int t = threadIdx.x;
    if (t < 9) a[t] = kA[b*9 + t];
    __syncthreads();
    if (t < 100) {
        float s = b1a[t];
        #pragma unroll
        for (int i = 0; i < 9; i++) s += a[i] * w1a[i*100 + t];
        h1[t] = gelu_exact(s);
    } else if (t < 200) {
        int h = t - 100;
        float s = b1b[h];
        #pragma unroll
        for (int i = 0; i < 9; i++) s += a[i] * w1b[i*100 + h];
        h2[h] = gelu_exact(s);
    }
    __syncthreads();
    for (int o = t; o < 147; o += blockDim.x) {
        float s1 = b2a[o], s2 = b2b[o];
        for (int h = 0; h < 100; h++) {
            s1 += h1[h] * w2a[h*147 + o];
            s2 += h2[h] * w2b[h*147 + o];
        }
        g_w1[b*147 + o] = s1;
        g_w2[b*147 + o] = s2;
    }
}

// ---------------- ConvTranspose chain (pixel-major layouts) ----------------
__global__ void ct1_kernel(const float* __restrict__ kA,
                           const float* __restrict__ w, const float* __restrict__ bias) {
    int b = blockIdx.x;
    __shared__ float a[9];
    if (threadIdx.x < 9) a[threadIdx.x] = kA[b*9 + threadIdx.x];
    __syncthreads();
    for (int el = threadIdx.x; el < 32*25; el += blockDim.x) {
        int pix = el >> 5, o = el & 31;
        int y = pix / 5, x = pix % 5;
        float acc = bias[o];
        int kys[2], iys[2], nky, kxs[2], ixs[2], nkx;
        if (y & 1) { nky = 2; kys[0]=0; iys[0]=(y+1)>>1; kys[1]=2; iys[1]=(y-1)>>1; }
        else       { nky = 1; kys[0]=1; iys[0]=y>>1; }
        if (x & 1) { nkx = 2; kxs[0]=0; ixs[0]=(x+1)>>1; kxs[1]=2; ixs[1]=(x-1)>>1; }
        else       { nkx = 1; kxs[0]=1; ixs[0]=x>>1; }
        for (int p = 0; p < nky; p++)
            for (int q = 0; q < nkx; q++)
                acc += a[iys[p]*3 + ixs[q]] * w[o*9 + kys[p]*3 + kxs[q]];
        g_a1[(b*25 + pix)*32 + o] = gelu_exact(acc);
    }
}

template <int IN_H>
__global__ void __launch_bounds__(256) ct_mid_kernel(const float* __restrict__ in,
                              const float* __restrict__ w,
                              const float* __restrict__ bias, float* __restrict__ out) {
    constexpr int OUT_H = 2*IN_H - 1;
    constexpr int IN_SZ = IN_H*IN_H;
    constexpr int OUT_SZ = OUT_H*OUT_H;
    __shared__ float s_in[IN_SZ*32];
    __shared__ float s_w[9*8*32];
    __shared__ float s_b[8];
    int b = blockIdx.x, og = blockIdx.y, tid = threadIdx.x;
    int o_base = og * 8;
    const float4* gin = (const float4*)(in + (size_t)b * IN_SZ * 32);
    float4* s_in4w = (float4*)s_in;
    for (int idx = tid; idx < IN_SZ*8; idx += 256) s_in4w[idx] = gin[idx];
    for (int idx = tid; idx < 2304; idx += 256) {
        int k = idx >> 8, r = idx & 255, ol = r >> 5, i = r & 31;
        s_w[idx] = w[(i*32 + o_base + ol)*9 + k];
    }
    if (tid < 8) s_b[tid] = bias[o_base + tid];
    __syncthreads();

    const float4* s_in4 = (const float4*)s_in;
    const float4* s_w4  = (const float4*)s_w;
    for (int pix = tid; pix < OUT_SZ; pix += 256) {
        int y = pix / OUT_H, x = pix % OUT_H;
        float acc[8];
        #pragma unroll
        for (int ol = 0; ol < 8; ol++) acc[ol] = s_b[ol];
        int kys[2], iys[2], nky, kxs[2], ixs[2], nkx;
        if (y & 1) { nky = 2; kys[0]=0; iys[0]=(y+1)>>1; kys[1]=2; iys[1]=(y-1)>>1; }
        else       { nky = 1; kys[0]=1; iys[0]=y>>1; }
        if (x & 1) { nkx = 2; kxs[0]=0; ixs[0]=(x+1)>>1; kxs[1]=2; ixs[1]=(x-1)>>1; }
        else       { nkx = 1; kxs[0]=1; ixs[0]=x>>1; }
        for (int p = 0; p < nky; p++)
            for (int q = 0; q < nkx; q++) {
                int base4 = (iys[p]*IN_H + ixs[q]) * 8;
                int kk = kys[p]*3 + kxs[q];
                #pragma unroll
                for (int c4 = 0; c4 < 8; c4++) {
                    float4 v = s_in4[base4 + c4];
                    #pragma unroll
                    for (int ol = 0; ol < 8; ol++) {
                        float4 wv = s_w4[kk*64 + ol*8 + c4];
                        acc[ol] += v.x*wv.x + v.y*wv.y + v.z*wv.z + v.w*wv.w;
                    }
                }
            }
        float* ob = out + ((size_t)(b*OUT_SZ + pix))*32 + o_base;
        float4 o0 = {gelu_exact(acc[0]), gelu_exact(acc[1]), gelu_exact(acc[2]), gelu_exact(acc[3])};
        float4 o1 = {gelu_exact(acc[4]), gelu_exact(acc[5]), gelu_exact(acc[6]), gelu_exact(acc[7])};
        *(float4*)(ob)     = o0;
        *(float4*)(ob + 4) = o1;
    }
}

__global__ void __launch_bounds__(256) ct5_kernel(const float* __restrict__ w, const float* __restrict__ bias) {
    __shared__ float s_w[9*2*32];
    int b = blockIdx.x, tid = threadIdx.x;
    for (int idx = tid; idx < 576; idx += 256) {
        int k = idx / 64, r = idx & 63, o = r >> 5, i = r & 31;
        s_w[idx] = w[i*18 + o*9 + k];
    }
    __syncthreads();
    float b0 = bias[0], b1 = bias[1];
    const float4* s_w4 = (const float4*)s_w;
    const float4* gin = (const float4*)(g_a4 + (size_t)b * 1089 * 32);
    for (int pix = tid; pix < NP; pix += 256) {
        int y = pix / NN, x = pix % NN;
        float acc0 = b0, acc1 = b1;
        int kys[2], iys[2], nky, kxs[2], ixs[2], nkx;
        if (y & 1) { nky = 1; kys[0]=1; iys[0]=(y+1)>>1; }
        else       { nky = 2; kys[0]=0; iys[0]=(y+2)>>1; kys[1]=2; iys[1]=y>>1; }
        if (x & 1) { nkx = 1; kxs[0]=1; ixs[0]=(x+1)>>1; }
        else       { nkx = 2; kxs[0]=0; ixs[0]=(x+2)>>1; kxs[1]=2; ixs[1]=x>>1; }
        for (int p = 0; p < nky; p++)
            for (int q = 0; q < nkx; q++) {
                int base4 = (iys[p]*33 + ixs[q]) * 8;
                int kk = kys[p]*3 + kxs[q];
                #pragma unroll
                for (int c4 = 0; c4 < 8; c4++) {
                    float4 v = __ldg(gin + base4 + c4);
                    float4 w0 = s_w4[kk*16 + c4];
                    float4 w1 = s_w4[kk*16 + 8 + c4];
                    acc0 += v.x*w0.x + v.y*w0.y + v.z*w0.z + v.w*w0.w;
                    acc1 += v.x*w1.x + v.y*w1.y + v.z*w1.z + v.w*w1.w;
                }
            }
        g_h[((size_t)b*2 + 0)*NP + pix] = acc0;
        g_h[((size_t)b*2 + 1)*NP + pix] = acc1;
    }
}

// ---------------- persistent per-sample solver (2 blocks/SM) ----------------
// smem floats:
#define OFF_SXP 0                      // 65x68 = 4420
#define OFF_SRP 4420                   // 69x72 = 4968
#define OFF_UNI (OFF_SRP + 4968)       // union: t-buf 4968 | Pr2048+Pi2048+Cr2016+Ci2016 = 8128
#define OFF_WCR (OFF_UNI + 8128)       // 2016
#define OFF_WCI (OFF_WCR + 2016)       // 2016
#define OFF_CT  (OFF_WCI + 2016)       // 33x64 = 2112
#define OFF_ST  (OFF_CT + 2112)        // 2112
#define OFF_W1  (OFF_ST + 2112)        // 160
#define OFF_W2  (OFF_W1 + 160)         // 160
#define OFF_KA  (OFF_W2 + 160)         // 16
#define SMEM_FLOATS (OFF_KA + 16)      // 26108 floats = 104432 B

__global__ void __launch_bounds__(512, 2) solver_kernel(const float* __restrict__ x_in,
                              const float* __restrict__ f_in,
                              const float* __restrict__ kA) {
    extern __shared__ float sm[];
    float* sxp  = sm + OFF_SXP;
    float* srp  = sm + OFF_SRP;
    float* sT   = sm + OFF_UNI;          // smoother mid, one channel
    float* sPr  = sm + OFF_UNI;          // [k2][64]
    float* sPi  = sm + OFF_UNI + 2048;
    float* sCr  = sm + OFF_UNI + 4096;   // [k1][32]
    float* sCi  = sm + OFF_UNI + 6112;
    float* sDr  = sPr;                   // [m][32] overlays P
    float* sDi  = sPi;
    float* swcr = sm + OFF_WCR;
    float* swci = sm + OFF_WCI;
    float* sct  = sm + OFF_CT;
    float* sst  = sm + OFF_ST;
    float* sw1  = sm + OFF_W1;
    float* sw2  = sm + OFF_W2;
    float* ska  = sm + OFF_KA;

    int b = blockIdx.x, tid = threadIdx.x;
    const int T = 512;
    const float inv = 0.12598815766974242f;  // 1/sqrt(63)

    // ---- init ----
    float fr[8];
    #pragma unroll
    for (int p = 0; p < 8; p++) {
        int el = tid + p*T;
        fr[p] = 0.f;
        if (el < NP64) {
            int i = el >> 6, j = el & 63;
            if (j < 63) {
                fr[p] = f_in[b*NP + i*NN + j];
                sxp[(i+1)*68 + (j+1)] = x_in[b*NP + i*NN + j];
            }
        }
    }
    for (int el = tid; el < 33*64; el += T) {
        sct[el] = g_cosT[el];
        sst[el] = g_sinT[el];
    }
    for (int c = tid; c < 65; c += T) {
        sxp[c] = (c == 64) ? 1.f : 0.f;
        sxp[64*68 + c] = 1.f;
    }
    for (int r = tid; r < 65; r += T) {
        sxp[r*68] = (r == 64) ? 1.f : 0.f;
        sxp[r*68 + 64] = 1.f;
    }
    for (int el = tid; el < 4968; el += T) srp[el] = 0.f;
    for (int el = tid; el < 2016; el += T) {
        int k1 = el >> 5, k2 = el & 31;
        int pix = k1*NN + k2;
        swcr[el] = g_h[(size_t)b*2*NP + 2*pix];
        swci[el] = g_h[(size_t)b*2*NP + 2*pix + 1];
    }
    if (tid < 9) ska[tid] = kA[b*9 + tid];
    for (int el = tid; el < 147; el += T) {
        sw1[el] = g_w1[b*147 + el];
        sw2[el] = g_w2[b*147 + el];
    }
    __syncthreads();

    for (int iter = 0; iter < 5; iter++) {
        // ---- (a) residual -> srp ; zero t-buffer ----
        #pragma unroll
        for (int p = 0; p < 8; p++) {
            int el = tid + p*T;
            if (el >= NP64) break;
            int i = el >> 6, j = el & 63;
            if (j >= 63) continue;
            const float* xb = sxp + i*68 + j;
            float acc = ska[0]*xb[0] + ska[1]*xb[1] + ska[2]*xb[2]
                      + ska[3]*xb[68] + ska[4]*xb[69] + ska[5]*xb[70]
                      + ska[6]*xb[136] + ska[7]*xb[137] + ska[8]*xb[138];
            srp[(i+3)*72 + j + 4] = fr[p] - acc;
        }
        for (int el = tid; el < 4968; el += T) sT[el] = 0.f;
        __syncthreads();

        // ---- smoother: one channel at a time ----
        for (int c = 0; c < ML; c++) {
            // stage1: t = conv7(r, w1[c])
            for (int w = tid; w < 1024; w += T) {
                int i = w >> 4, g = w & 15;
                if (i >= 63) continue;
                int j0 = g << 2;
                float a0=0.f, a1=0.f, a2=0.f, a3=0.f;
                const float* wc_ = sw1 + c*49;
                #pragma unroll
                for (int u = 0; u < 7; u++) {
                    const float4* rp = (const float4*)(srp + (i+u)*72 + j0);
                    float4 A = rp[0], B = rp[1], C = rp[2];
                    float rr[12] = {A.x,A.y,A.z,A.w, B.x,B.y,B.z,B.w, C.x,C.y,C.z,C.w};
                    #pragma unroll
                    for (int v = 0; v < 7; v++) {
                        float wv = wc_[u*7 + v];
                        a0 += rr[v+1]*wv; a1 += rr[v+2]*wv;
                        a2 += rr[v+3]*wv; a3 += rr[v+4]*wv;
                    }
                }
                float* o = sT + (i+3)*72 + j0 + 4;
                if (g < 15) { float4 ov = {a0,a1,a2,a3}; *(float4*)o = ov; }
                else { o[0]=a0; o[1]=a1; o[2]=a2; }
            }
            __syncthreads();
            // stage2: x += conv7(t, w2[c])
            for (int w = tid; w < 1024; w += T) {
                int i = w >> 4, g = w & 15;
                if (i >= 63) continue;
                int j0 = g << 2;
                float a0=0.f, a1=0.f, a2=0.f, a3=0.f;
                const float* wc_ = sw2 + c*49;
                #pragma unroll
                for (int u = 0; u < 7; u++) {
                    const float4* rp = (const float4*)(sT + (i+u)*72 + j0);
                    float4 A = rp[0], B = rp[1], C = rp[2];
                    float rr[12] = {A.x,A.y,A.z,A.w, B.x,B.y,B.z,B.w, C.x,C.y,C.z,C.w};
                    #pragma unroll
                    for (int v = 0; v < 7; v++) {
                        float wv = wc_[u*7 + v];
                        a0 += rr[v+1]*wv; a1 += rr[v+2]*wv;
                        a2 += rr[v+3]*wv; a3 += rr[v+4]*wv;
                    }
                }
                float* xo = sxp + (i+1)*68 + j0 + 1;
                xo[0] += a0; xo[1] += a1; xo[2] += a2;
                if (g < 15) xo[3] += a3;
            }
            __syncthreads();
        }

        // ---- (d) residual -> srp ----
        #pragma unroll
        for (int p = 0; p < 8; p++) {
            int el = tid + p*T;
            if (el >= NP64) break;
            int i = el >> 6, j = el & 63;
            if (j >= 63) continue;
            const float* xb = sxp + i*68 + j;
            float acc = ska[0]*xb[0] + ska[1]*xb[1] + ska[2]*xb[2]
                      + ska[3]*xb[68] + ska[4]*xb[69] + ska[5]*xb[70]
                      + ska[6]*xb[136] + ska[7]*xb[137] + ska[8]*xb[138];
            srp[(i+3)*72 + j + 4] = fr[p] - acc;
        }
        __syncthreads();

        // ---- (P) P[k2][m] = inv * sum_n r[m,n] conj(W[k2,n]), k2<32 ----
        for (int w = tid; w < 2048; w += T) {
            int k2 = w >> 6, m = w & 63;
            if (m >= 63) continue;
            const float4* rrow = (const float4*)(srp + (m+3)*72 + 4);
            const float4* cR = (const float4*)(sct + k2*64);
            const float4* sR = (const float4*)(sst + k2*64);
            float ar = 0.f, ai = 0.f;
            #pragma unroll 4
            for (int n4 = 0; n4 < 16; n4++) {
                float4 rv = rrow[n4];
                float4 c4 = cR[n4];
                float4 s4 = sR[n4];
                ar += c4.x*rv.x + c4.y*rv.y + c4.z*rv.z + c4.w*rv.w;
                ai -= s4.x*rv.x + s4.y*rv.y + s4.z*rv.z + s4.w*rv.w;
            }
            sPr[k2*64 + m] = ar * inv;
            sPi[k2*64 + m] = ai * inv;
        }
        __syncthreads();

        // ---- (C) C[k1][k2] = (inv * sum_m conj(W[k1,m]) P[m,k2]) * wc ----
        for (int w = tid; w < 2016; w += T) {
            int k1 = w >> 5, k2 = w & 31;
            float ar = 0.f, ai = 0.f;
            const float4* pR = (const float4*)(sPr + k2*64);
            const float4* qR = (const float4*)(sPi + k2*64);
            if (k1 <= 32) {
                const float4* cR = (const float4*)(sct + k1*64);
                const float4* sR = (const float4*)(sst + k1*64);
                #pragma unroll 4
                for (int m4 = 0; m4 < 16; m4++) {
                    float4 c4 = cR[m4], s4 = sR[m4], p4 = pR[m4], q4 = qR[m4];
                    ar += c4.x*p4.x + s4.x*q4.x;  ai += c4.x*q4.x - s4.x*p4.x;
                    ar += c4.y*p4.y + s4.y*q4.y;  ai += c4.y*q4.y - s4.y*p4.y;
                    ar += c4.z*p4.z + s4.z*q4.z;  ai += c4.z*q4.z - s4.z*p4.z;
                    ar += c4.w*p4.w + s4.w*q4.w;  ai += c4.w*q4.w - s4.w*p4.w;
                }
            } else {
                const float4* cR = (const float4*)(sct + (63-k1)*64);
                const float4* sR = (const float4*)(sst + (63-k1)*64);
                #pragma unroll 4
                for (int m4 = 0; m4 < 16; m4++) {
                    float4 c4 = cR[m4], s4 = sR[m4], p4 = pR[m4], q4 = qR[m4];
                    ar += c4.x*p4.x - s4.x*q4.x;  ai += c4.x*q4.x + s4.x*p4.x;
                    ar += c4.y*p4.y - s4.y*q4.y;  ai += c4.y*q4.y + s4.y*p4.y;
                    ar += c4.z*p4.z - s4.z*q4.z;  ai += c4.z*q4.z + s4.z*p4.z;
                    ar += c4.w*p4.w - s4.w*q4.w;  ai += c4.w*q4.w + s4.w*p4.w;
                }
            }
            ar *= inv; ai *= inv;
            float wr = swcr[w], wi = swci[w];
            sCr[w] = ar*wr - ai*wi;
            sCi[w] = ar*wi + ai*wr;
        }
        __syncthreads();

        // ---- (D) D[m][k2] = inv * sum_k1 W[m,k1] C[k1,k2] ----
        for (int w = tid; w < 2016; w += T) {
            int m = w >> 5, k2 = w & 31;
            float ar = 0.f, ai = 0.f;
            if (m <= 32) {
                const float4* cR = (const float4*)(sct + m*64);
                const float4* sR = (const float4*)(sst + m*64);
                #pragma unroll 4
                for (int kc = 0; kc < 16; kc++) {
                    float4 c4 = cR[kc], s4 = sR[kc];
                    int k1 = kc << 2;
                    float cr0 = sCr[(k1+0)*32+k2], ci0 = sCi[(k1+0)*32+k2];
                    float cr1 = sCr[(k1+1)*32+k2], ci1 = sCi[(k1+1)*32+k2];
                    float cr2 = sCr[(k1+2)*32+k2], ci2 = sCi[(k1+2)*32+k2];
                    float cr3 = sCr[(k1+3)*32+k2], ci3 = sCi[(k1+3)*32+k2];
                    ar += c4.x*cr0 - s4.x*ci0;  ai += c4.x*ci0 + s4.x*cr0;
                    ar += c4.y*cr1 - s4.y*ci1;  ai += c4.y*ci1 + s4.y*cr1;
                    ar += c4.z*cr2 - s4.z*ci2;  ai += c4.z*ci2 + s4.z*cr2;
                    ar += c4.w*cr3 - s4.w*ci3;  ai += c4.w*ci3 + s4.w*cr3;
                }
            } else {
                const float4* cR = (const float4*)(sct + (63-m)*64);
                const float4* sR = (const float4*)(sst + (63-m)*64);
                #pragma unroll 4
                for (int kc = 0; kc < 16; kc++) {
                    float4 c4 = cR[kc], s4 = sR[kc];
                    int k1 = kc << 2;
                    float cr0 = sCr[(k1+0)*32+k2], ci0 = sCi[(k1+0)*32+k2];
                    float cr1 = sCr[(k1+1)*32+k2], ci1 = sCi[(k1+1)*32+k2];
                    float cr2 = sCr[(k1+2)*32+k2], ci2 = sCi[(k1+2)*32+k2];
                    float cr3 = sCr[(k1+3)*32+k2], ci3 = sCi[(k1+3)*32+k2];
                    ar += c4.x*cr0 + s4.x*ci0;  ai += c4.x*ci0 - s4.x*cr0;
                    ar += c4.y*cr1 + s4.y*ci1;  ai += c4.y*ci1 - s4.y*cr1;
                    ar += c4.z*cr2 + s4.z*ci2;  ai += c4.z*ci2 - s4.z*cr2;
                    ar += c4.w*cr3 + s4.w*ci3;  ai += c4.w*ci3 - s4.w*cr3;
                }
            }
            sDr[w] = ar * inv;
            sDi[w] = ai * inv;
        }
        __syncthreads();

        // ---- (h) x[m,n] += inv*(Dr[m,0] + 2*sum_{k2=1..31} Re(D[m,k2] e^{i th})) ----
        for (int w = tid; w < 1024; w += T) {
            int m = w >> 4, g = w & 15;
            if (m >= 63) continue;
            int n0 = g << 2;
            const float* dr_ = sDr + m*32;
            const float* di_ = sDi + m*32;
            float d0 = dr_[0];
            float ax=d0, ay=d0, az=d0, aw=d0;
            #pragma unroll 8
            for (int k2 = 1; k2 < 32; k2++) {
                float dr2 = dr_[k2]*2.f, di2 = di_[k2]*2.f;
                float4 c4 = *(const float4*)(sct + k2*64 + n0);
                float4 s4 = *(const float4*)(sst + k2*64 + n0);
                ax += dr2*c4.x - di2*s4.x;
                ay += dr2*c4.y - di2*s4.y;
                az += dr2*c4.z - di2*s4.z;
                aw += dr2*c4.w - di2*s4.w;
            }
            float* xo = sxp + (m+1)*68 + n0 + 1;
            xo[0] += ax*inv; xo[1] += ay*inv; xo[2] += az*inv;
            if (g < 15) xo[3] += aw*inv;
        }
        __syncthreads();
    }

    // ---- final residual + sum of squares ----
    float loc = 0.f;
    #pragma unroll
    for (int p = 0; p < 8; p++) {
        int el = tid + p*T;
        if (el >= NP64) break;
        int i = el >> 6, j = el & 63;
        if (j >= 63) continue;
        const float* xb = sxp + i*68 + j;
        float acc = ska[0]*xb[0] + ska[1]*xb[1] + ska[2]*xb[2]
                  + ska[3]*xb[68] + ska[4]*xb[69] + ska[5]*xb[70]
                  + ska[6]*xb[136] + ska[7]*xb[137] + ska[8]*xb[138];
        float v = fr[p] - acc;
        loc += v * v;
    }
    #pragma unroll
    for (int off = 16; off; off >>= 1)
        loc += __shfl_xor_sync(0xFFFFFFFFu, loc, off);
    __shared__ float wsum[16];
    int wid = tid >> 5;
    if ((tid & 31) == 0) wsum[wid] = loc;
    __syncthreads();
    if (tid == 0) {
        float s = 0.f;
        #pragma unroll
        for (int w = 0; w < 16; w++) s += wsum[w];
        g_blocksum[b] = s;
    }
}

__global__ void final_reduce_kernel(float* __restrict__ out) {
    __shared__ float s[BATCH];
    s[threadIdx.x] = g_blocksum[threadIdx.x];
    __syncthreads();
    for (int st = BATCH/2; st > 0; st >>= 1) {
        if (threadIdx.x < st) s[threadIdx.x] += s[threadIdx.x + st];
        __syncthreads();
    }
    if (threadIdx.x == 0) out[0] = sqrtf(s[0]) / 256.0f;
}

// ---------------- host ----------------
extern "C" void kernel_launch(void* const* d_in, const int* in_sizes, int n_in,
                              void* d_out, int out_size) {
    const float* x      = (const float*)d_in[0];
    const float* f      = (const float*)d_in[1];
    const float* kA     = (const float*)d_in[2];
    const float* fc1_w1 = (const float*)d_in[3];
    const float* fc1_b1 = (const float*)d_in[4];
    const float* fc1_w2 = (const float*)d_in[5];
    const float* fc1_b2 = (const float*)d_in[6];
    const float* fc2_w1 = (const float*)d_in[7];
    const float* fc2_b1 = (const float*)d_in[8];
    const float* fc2_w2 = (const float*)d_in[9];
    const float* fc2_b2 = (const float*)d_in[10];
    const float* ct1_w  = (const float*)d_in[11];
    const float* ct1_b  = (const float*)d_in[12];
    const float* ct2_w  = (const float*)d_in[13];
    const float* ct2_b  = (const float*)d_in[14];
    const float* ct3_w  = (const float*)d_in[15];
    const float* ct3_b  = (const float*)d_in[16];
    const float* ct4_w  = (const float*)d_in[17];
    const float* ct4_b  = (const float*)d_in[18];
    const float* ct5_w  = (const float*)d_in[19];
    const float* ct5_b  = (const float*)d_in[20];
    float* out = (float*)d_out;

    cudaFuncSetAttribute(solver_kernel, cudaFuncAttributeMaxDynamicSharedMemorySize,
                         SMEM_FLOATS * (int)sizeof(float));

    init_tw_kernel<<<(33*64 + 255)/256, 256>>>();
    hyper_kernel<<<BATCH, 256>>>(kA, fc1_w1, fc1_b1, fc1_w2, fc1_b2,
                                 fc2_w1, fc2_b1, fc2_w2, fc2_b2);
    ct1_kernel<<<BATCH, 256>>>(kA, ct1_w, ct1_b);
    ct_mid_kernel<5> <<<dim3(BATCH, 4), 256>>>(g_a1, ct2_w, ct2_b, g_a2);
    ct_mid_kernel<9> <<<dim3(BATCH, 4), 256>>>(g_a2, ct3_w, ct3_b, g_a3);
    ct_mid_kernel<17><<<dim3(BATCH, 4), 256>>>(g_a3, ct4_w, ct4_b, g_a4);
    ct5_kernel<<<BATCH, 256>>>(ct5_w, ct5_b);
    solver_kernel<<<BATCH, 512, SMEM_FLOATS * sizeof(float)>>>(x, f, kA);
    final_reduce_kernel<<<1, BATCH>>>(out);
}

// round 4
// speedup vs baseline: 1.1768x; 1.1768x over previous
#include <cuda_runtime.h>
#include <math.h>

#define NN 63
#define NP (NN*NN)          // 3969
#define NP64 4032
#define BATCH 256
#define KS 7
#define ML 3

// ---------------- device scratch ----------------
__device__ float g_cosT[33*64];     // row-major, rows 0..32, col63=0
__device__ float g_sinT[33*64];
__device__ float g_cosTT[63*32];    // transposed [n][k2<32]
__device__ float g_sinTT[63*32];
__device__ float g_w1[BATCH*147];
__device__ float g_w2[BATCH*147];
__device__ float g_a1[BATCH*25*32];
__device__ float g_a2[BATCH*81*32];
__device__ float g_a3[BATCH*289*32];
__device__ float g_a4[BATCH*1089*32];
__device__ float g_h [BATCH*2*NP];
__device__ float g_blocksum[BATCH];

__device__ __forceinline__ float gelu_exact(float v) {
    return v * 0.5f * (1.0f + erff(v * 0.70710678118654752f));
}

__global__ void init_tw_kernel() {
    int idx = blockIdx.x * blockDim.x + threadIdx.x;
    if (idx < 33*64) {
        int k = idx >> 6, n = idx & 63;
        if (n < 63) {
            float ang = 6.28318530717958647692f * (float)((k * n) % NN) / 63.0f;
            g_cosT[idx] = cosf(ang);
            g_sinT[idx] = sinf(ang);
        } else { g_cosT[idx] = 0.f; g_sinT[idx] = 0.f; }
    }
    if (idx < 63*32) {
        int n = idx >> 5, k2 = idx & 31;
        float ang = 6.28318530717958647692f * (float)((k2 * n) % NN) / 63.0f;
        g_cosTT[idx] = cosf(ang);
        g_sinTT[idx] = sinf(ang);
    }
}

// ---------------- hypernet ----------------
__global__ void hyper_kernel(const float* __restrict__ kA,
                             const float* __restrict__ w1a, const float* __restrict__ b1a,
                             const float* __restrict__ w2a, const float* __restrict__ b2a,
                             const float* __restrict__ w1b, const float* __restrict__ b1b,
                             const float* __restrict__ w2b, const float* __restrict__ b2b) {
    int b = blockIdx.x;
    __shared__ float a[9], h1[100], h2[100];
    int t = threadIdx.x;
    if (t < 9) a[t] = kA[b*9 + t];
    __syncthreads();
    if (t < 100) {
        float s = b1a[t];
        #pragma unroll
        for (int i = 0; i < 9; i++) s += a[i] * w1a[i*100 + t];
        h1[t] = gelu_exact(s);
    } else if (t < 200) {
        int h = t - 100;
        float s = b1b[h];
        #pragma unroll
        for (int i = 0; i < 9; i++) s += a[i] * w1b[i*100 + h];
        h2[h] = gelu_exact(s);
    }
    __syncthreads();
    for (int o = t; o < 147; o += blockDim.x) {
        float s1 = b2a[o], s2 = b2b[o];
        for (int h = 0; h < 100; h++) {
            s1 += h1[h] * w2a[h*147 + o];
            s2 += h2[h] * w2b[h*147 + o];
        }
        g_w1[b*147 + o] = s1;
        g_w2[b*147 + o] = s2;
    }
}

// ---------------- ConvTranspose chain ----------------
__global__ void ct1_kernel(const float* __restrict__ kA,
                           const float* __restrict__ w, const float* __restrict__ bias) {
    int b = blockIdx.x;
    __shared__ float a[9];
    if (threadIdx.x < 9) a[threadIdx.x] = kA[b*9 + threadIdx.x];
    __syncthreads();
    for (int el = threadIdx.x; el < 32*25; el += blockDim.x) {
        int pix = el >> 5, o = el & 31;
        int y = pix / 5, x = pix % 5;
        float acc = bias[o];
        int kys[2], iys[2], nky, kxs[2], ixs[2], nkx;
        if (y & 1) { nky = 2; kys[0]=0; iys[0]=(y+1)>>1; kys[1]=2; iys[1]=(y-1)>>1; }
        else       { nky = 1; kys[0]=1; iys[0]=y>>1; }
        if (x & 1) { nkx = 2; kxs[0]=0; ixs[0]=(x+1)>>1; kxs[1]=2; ixs[1]=(x-1)>>1; }
        else       { nkx = 1; kxs[0]=1; ixs[0]=x>>1; }
        for (int p = 0; p < nky; p++)
            for (int q = 0; q < nkx; q++)
                acc += a[iys[p]*3 + ixs[q]] * w[o*9 + kys[p]*3 + kxs[q]];
        g_a1[(b*25 + pix)*32 + o] = gelu_exact(acc);
    }
}

template <int IN_H>
__global__ void __launch_bounds__(256) ct_mid_kernel(const float* __restrict__ in,
                              const float* __restrict__ w,
                              const float* __restrict__ bias, float* __restrict__ out) {
    constexpr int OUT_H = 2*IN_H - 1;
    constexpr int IN_SZ = IN_H*IN_H;
    constexpr int OUT_SZ = OUT_H*OUT_H;
    __shared__ float s_in[IN_SZ*32];
    __shared__ float s_w[9*8*32];
    __shared__ float s_b[8];
    int b = blockIdx.x, og = blockIdx.y, tid = threadIdx.x;
    int o_base = og * 8;
    const float4* gin = (const float4*)(in + (size_t)b * IN_SZ * 32);
    float4* s_in4w = (float4*)s_in;
    for (int idx = tid; idx < IN_SZ*8; idx += 256) s_in4w[idx] = gin[idx];
    for (int idx = tid; idx < 2304; idx += 256) {
        int k = idx >> 8, r = idx & 255, ol = r >> 5, i = r & 31;
        s_w[idx] = w[(i*32 + o_base + ol)*9 + k];
    }
    if (tid < 8) s_b[tid] = bias[o_base + tid];
    __syncthreads();

    const float4* s_in4 = (const float4*)s_in;
    const float4* s_w4  = (const float4*)s_w;
    for (int pix = tid; pix < OUT_SZ; pix += 256) {
        int y = pix / OUT_H, x = pix % OUT_H;
        float acc[8];
        #pragma unroll
        for (int ol = 0; ol < 8; ol++) acc[ol] = s_b[ol];
        int kys[2], iys[2], nky, kxs[2], ixs[2], nkx;
        if (y & 1) { nky = 2; kys[0]=0; iys[0]=(y+1)>>1; kys[1]=2; iys[1]=(y-1)>>1; }
        else       { nky = 1; kys[0]=1; iys[0]=y>>1; }
        if (x & 1) { nkx = 2; kxs[0]=0; ixs[0]=(x+1)>>1; kxs[1]=2; ixs[1]=(x-1)>>1; }
        else       { nkx = 1; kxs[0]=1; ixs[0]=x>>1; }
        for (int p = 0; p < nky; p++)
            for (int q = 0; q < nkx; q++) {
                int base4 = (iys[p]*IN_H + ixs[q]) * 8;
                int kk = kys[p]*3 + kxs[q];
                #pragma unroll
                for (int c4 = 0; c4 < 8; c4++) {
                    float4 v = s_in4[base4 + c4];
                    #pragma unroll
                    for (int ol = 0; ol < 8; ol++) {
                        float4 wv = s_w4[kk*64 + ol*8 + c4];
                        acc[ol] += v.x*wv.x + v.y*wv.y + v.z*wv.z + v.w*wv.w;
                    }
                }
            }
        float* ob = out + ((size_t)(b*OUT_SZ + pix))*32 + o_base;
        float4 o0 = {gelu_exact(acc[0]), gelu_exact(acc[1]), gelu_exact(acc[2]), gelu_exact(acc[3])};
        float4 o1 = {gelu_exact(acc[4]), gelu_exact(acc[5]), gelu_exact(acc[6]), gelu_exact(acc[7])};
        *(float4*)(ob)     = o0;
        *(float4*)(ob + 4) = o1;
    }
}

__global__ void __launch_bounds__(256) ct5_kernel(const float* __restrict__ w, const float* __restrict__ bias) {
    __shared__ float s_w[9*2*32];
    int b = blockIdx.x, tid = threadIdx.x;
    for (int idx = tid; idx < 576; idx += 256) {
        int k = idx / 64, r = idx & 63, o = r >> 5, i = r & 31;
        s_w[idx] = w[i*18 + o*9 + k];
    }
    __syncthreads();
    float b0 = bias[0], b1 = bias[1];
    const float4* s_w4 = (const float4*)s_w;
    const float4* gin = (const float4*)(g_a4 + (size_t)b * 1089 * 32);
    for (int pix = tid; pix < NP; pix += 256) {
        int y = pix / NN, x = pix % NN;
        float acc0 = b0, acc1 = b1;
        int kys[2], iys[2], nky, kxs[2], ixs[2], nkx;
        if (y & 1) { nky = 1; kys[0]=1; iys[0]=(y+1)>>1; }
        else       { nky = 2; kys[0]=0; iys[0]=(y+2)>>1; kys[1]=2; iys[1]=y>>1; }
        if (x & 1) { nkx = 1; kxs[0]=1; ixs[0]=(x+1)>>1; }
        else       { nkx = 2; kxs[0]=0; ixs[0]=(x+2)>>1; kxs[1]=2; ixs[1]=x>>1; }
        for (int p = 0; p < nky; p++)
            for (int q = 0; q < nkx; q++) {
                int base4 = (iys[p]*33 + ixs[q]) * 8;
                int kk = kys[p]*3 + kxs[q];
                #pragma unroll
                for (int c4 = 0; c4 < 8; c4++) {
                    float4 v = __ldg(gin + base4 + c4);
                    float4 w0 = s_w4[kk*16 + c4];
                    float4 w1 = s_w4[kk*16 + 8 + c4];
                    acc0 += v.x*w0.x + v.y*w0.y + v.z*w0.z + v.w*w0.w;
                    acc1 += v.x*w1.x + v.y*w1.y + v.z*w1.z + v.w*w1.w;
                }
            }
        g_h[((size_t)b*2 + 0)*NP + pix] = acc0;
        g_h[((size_t)b*2 + 1)*NP + pix] = acc1;
    }
}

// ---------------- persistent per-sample solver ----------------
#define OFF_SXP 0                        // 65x68 = 4420
#define OFF_SRP 4420                     // 69x72 = 4968
#define OFF_T   (OFF_SRP + 4968)         // 3*4968 = 14904
#define OFF_PR  (OFF_T + 14904)          // [32][64] 2048
#define OFF_PI  (OFF_PR + 2048)
#define OFF_CR  (OFF_PI + 2048)          // [63][32] 2016
#define OFF_CI  (OFF_CR + 2016)
#define OFF_DR  (OFF_CI + 2016)          // [63][32] 2016
#define OFF_DI  (OFF_DR + 2016)
#define OFF_WCR (OFF_DI + 2016)          // 2016
#define OFF_WCI (OFF_WCR + 2016)
#define OFF_MC  (OFF_WCI + 2016)         // [33][64] 2112
#define OFF_MS  (OFF_MC + 2112)
#define OFF_TTC (OFF_MS + 2112)          // [63][32] 2016
#define OFF_TTS (OFF_TTC + 2016)
#define OFF_W1  (OFF_TTS + 2016)         // 160
#define OFF_W2  (OFF_W1 + 160)
#define OFF_KA  (OFF_W2 + 160)
#define SMEM_FLOATS (OFF_KA + 16)        // 49076 floats = 196304 B

__global__ void __launch_bounds__(512) solver_kernel(const float* __restrict__ x_in,
                              const float* __restrict__ f_in,
                              const float* __restrict__ kA) {
    extern __shared__ float sm[];
    float* sxp  = sm + OFF_SXP;
    float* srp  = sm + OFF_SRP;
    float* sT   = sm + OFF_T;
    float* sPr  = sm + OFF_PR;
    float* sPi  = sm + OFF_PI;
    float* sCr  = sm + OFF_CR;
    float* sCi  = sm + OFF_CI;
    float* sDr  = sm + OFF_DR;
    float* sDi  = sm + OFF_DI;
    float* swcr = sm + OFF_WCR;
    float* swci = sm + OFF_WCI;
    float* smc  = sm + OFF_MC;
    float* sms  = sm + OFF_MS;
    float* sttc = sm + OFF_TTC;
    float* stts = sm + OFF_TTS;
    float* sw1  = sm + OFF_W1;
    float* sw2  = sm + OFF_W2;
    float* ska  = sm + OFF_KA;

    int b = blockIdx.x, tid = threadIdx.x;
    const int T = 512;
    const float inv = 0.12598815766974242f;  // 1/sqrt(63)

    // ---- init ----
    float fr[8];
    #pragma unroll
    for (int p = 0; p < 8; p++) {
        int el = tid + p*T;
        fr[p] = 0.f;
        if (el < NP64) {
            int i = el >> 6, j = el & 63;
            if (j < 63) {
                fr[p] = f_in[b*NP + i*NN + j];
                sxp[(i+1)*68 + (j+1)] = x_in[b*NP + i*NN + j];
            }
        }
    }
    for (int el = tid; el < 33*64; el += T) { smc[el] = g_cosT[el]; sms[el] = g_sinT[el]; }
    for (int el = tid; el < 63*32; el += T) { sttc[el] = g_cosTT[el]; stts[el] = g_sinTT[el]; }
    for (int c = tid; c < 65; c += T) {
        sxp[c] = (c == 64) ? 1.f : 0.f;
        sxp[64*68 + c] = 1.f;
    }
    for (int r = tid; r < 65; r += T) {
        sxp[r*68] = (r == 64) ? 1.f : 0.f;
        sxp[r*68 + 64] = 1.f;
    }
    for (int el = tid; el < 4968; el += T) srp[el] = 0.f;
    for (int el = tid; el < 14904; el += T) sT[el] = 0.f;
    for (int el = tid; el < 2016; el += T) {
        int k1 = el >> 5, k2 = el & 31;
        int pix = k1*NN + k2;
        swcr[el] = g_h[(size_t)b*2*NP + 2*pix];
        swci[el] = g_h[(size_t)b*2*NP + 2*pix + 1];
    }
    if (tid < 9) ska[tid] = kA[b*9 + tid];
    for (int el = tid; el < 147; el += T) {
        sw1[el] = g_w1[b*147 + el];
        sw2[el] = g_w2[b*147 + el];
    }
    __syncthreads();

    for (int iter = 0; iter < 5; iter++) {
        // ---- (a) residual -> srp ----
        #pragma unroll
        for (int p = 0; p < 8; p++) {
            int el = tid + p*T;
            if (el >= NP64) break;
            int i = el >> 6, j = el & 63;
            if (j >= 63) continue;
            const float* xb = sxp + i*68 + j;
            float acc = ska[0]*xb[0] + ska[1]*xb[1] + ska[2]*xb[2]
                      + ska[3]*xb[68] + ska[4]*xb[69] + ska[5]*xb[70]
                      + ska[6]*xb[136] + ska[7]*xb[137] + ska[8]*xb[138];
            srp[(i+3)*72 + j + 4] = fr[p] - acc;
        }
        __syncthreads();

        // ---- (b) stage1: t[c] = conv7(r, w1[c]) — channel-blocked, read r once ----
        for (int w = tid; w < 1024; w += T) {
            int i = w >> 4, g = w & 15;
            if (i >= 63) continue;
            int j0 = g << 2;
            float4 A0 = {0,0,0,0}, A1 = {0,0,0,0}, A2 = {0,0,0,0};
            #pragma unroll
            for (int u = 0; u < 7; u++) {
                const float4* rp = (const float4*)(srp + (i+u)*72 + j0);
                float4 Ra = rp[0], Rb = rp[1], Rc = rp[2];
                float rr[12] = {Ra.x,Ra.y,Ra.z,Ra.w, Rb.x,Rb.y,Rb.z,Rb.w, Rc.x,Rc.y,Rc.z,Rc.w};
                #pragma unroll
                for (int v = 0; v < 7; v++) {
                    float w0 = sw1[u*7 + v];
                    float w1 = sw1[49 + u*7 + v];
                    float w2 = sw1[98 + u*7 + v];
                    A0.x += rr[v+1]*w0; A0.y += rr[v+2]*w0; A0.z += rr[v+3]*w0; A0.w += rr[v+4]*w0;
                    A1.x += rr[v+1]*w1; A1.y += rr[v+2]*w1; A1.z += rr[v+3]*w1; A1.w += rr[v+4]*w1;
                    A2.x += rr[v+1]*w2; A2.y += rr[v+2]*w2; A2.z += rr[v+3]*w2; A2.w += rr[v+4]*w2;
                }
            }
            float* o0 = sT + (i+3)*72 + j0 + 4;
            float* o1 = o0 + 4968;
            float* o2 = o1 + 4968;
            if (g < 15) {
                *(float4*)o0 = A0; *(float4*)o1 = A1; *(float4*)o2 = A2;
            } else {
                o0[0]=A0.x; o0[1]=A0.y; o0[2]=A0.z;
                o1[0]=A1.x; o1[1]=A1.y; o1[2]=A1.z;
                o2[0]=A2.x; o2[1]=A2.y; o2[2]=A2.z;
            }
        }
        __syncthreads();

        // ---- (c) stage2: x += sum_c conv7(t[c], w2[c]) ----
        for (int w = tid; w < 1024; w += T) {
            int i = w >> 4, g = w & 15;
            if (i >= 63) continue;
            int j0 = g << 2;
            float a0=0.f, a1=0.f, a2=0.f, a3=0.f;
            #pragma unroll
            for (int c = 0; c < 3; c++) {
                const float* tb = sT + c*4968;
                const float* wc_ = sw2 + c*49;
                #pragma unroll
                for (int u = 0; u < 7; u++) {
                    const float4* rp = (const float4*)(tb + (i+u)*72 + j0);
                    float4 Ra = rp[0], Rb = rp[1], Rc = rp[2];
                    float rr[12] = {Ra.x,Ra.y,Ra.z,Ra.w, Rb.x,Rb.y,Rb.z,Rb.w, Rc.x,Rc.y,Rc.z,Rc.w};
                    #pragma unroll
                    for (int v = 0; v < 7; v++) {
                        float wv = wc_[u*7 + v];
                        a0 += rr[v+1]*wv; a1 += rr[v+2]*wv;
                        a2 += rr[v+3]*wv; a3 += rr[v+4]*wv;
                    }
                }
            }
            float* xo = sxp + (i+1)*68 + j0 + 1;
            xo[0] += a0; xo[1] += a1; xo[2] += a2;
            if (g < 15) xo[3] += a3;
        }
        __syncthreads();

        // ---- (d) residual -> srp ----
        #pragma unroll
        for (int p = 0; p < 8; p++) {
            int el = tid + p*T;
            if (el >= NP64) break;
            int i = el >> 6, j = el & 63;
            if (j >= 63) continue;
            const float* xb = sxp + i*68 + j;
            float acc = ska[0]*xb[0] + ska[1]*xb[1] + ska[2]*xb[2]
                      + ska[3]*xb[68] + ska[4]*xb[69] + ska[5]*xb[70]
                      + ska[6]*xb[136] + ska[7]*xb[137] + ska[8]*xb[138];
            srp[(i+3)*72 + j + 4] = fr[p] - acc;
        }
        __syncthreads();

        // ---- (P) P[k2][m] = inv * sum_n r[m,n] conj(W[k2,n]), k2<32; 2m x 4k2 ----
        {
            const float4* ttc4 = (const float4*)sttc;
            const float4* tts4 = (const float4*)stts;
            for (int w = tid; w < 256; w += T) {
                int mp = w >> 3, q = w & 7;
                int m0 = mp*2, m1 = m0+1;
                float4 ar0={0,0,0,0}, ai0={0,0,0,0}, ar1={0,0,0,0}, ai1={0,0,0,0};
                const float* r0p = srp + (m0+3)*72 + 4;
                const float* r1p = srp + (m1+3)*72 + 4;   // m1==63 -> halo row (zeros)
                #pragma unroll 9
                for (int n = 0; n < 63; n++) {
                    float r0 = r0p[n], r1 = r1p[n];
                    float4 c = ttc4[n*8 + q];
                    float4 s = tts4[n*8 + q];
                    ar0.x += r0*c.x; ar0.y += r0*c.y; ar0.z += r0*c.z; ar0.w += r0*c.w;
                    ai0.x -= r0*s.x; ai0.y -= r0*s.y; ai0.z -= r0*s.z; ai0.w -= r0*s.w;
                    ar1.x += r1*c.x; ar1.y += r1*c.y; ar1.z += r1*c.z; ar1.w += r1*c.w;
                    ai1.x -= r1*s.x; ai1.y -= r1*s.y; ai1.z -= r1*s.z; ai1.w -= r1*s.w;
                }
                int k20 = q << 2;
                sPr[(k20+0)*64 + m0] = ar0.x*inv;  sPr[(k20+0)*64 + m1] = ar1.x*inv;
                sPr[(k20+1)*64 + m0] = ar0.y*inv;  sPr[(k20+1)*64 + m1] = ar1.y*inv;
                sPr[(k20+2)*64 + m0] = ar0.z*inv;  sPr[(k20+2)*64 + m1] = ar1.z*inv;
                sPr[(k20+3)*64 + m0] = ar0.w*inv;  sPr[(k20+3)*64 + m1] = ar1.w*inv;
                sPi[(k20+0)*64 + m0] = ai0.x*inv;  sPi[(k20+0)*64 + m1] = ai1.x*inv;
                sPi[(k20+1)*64 + m0] = ai0.y*inv;  sPi[(k20+1)*64 + m1] = ai1.y*inv;
                sPi[(k20+2)*64 + m0] = ai0.z*inv;  sPi[(k20+2)*64 + m1] = ai1.z*inv;
                sPi[(k20+3)*64 + m0] = ai0.w*inv;  sPi[(k20+3)*64 + m1] = ai1.w*inv;
            }
        }
        __syncthreads();

        // ---- (C) C[k1][k2] = (inv * sum_m conj(W[k1,m]) P[k2][m]) * wc ; 2k1 x 4k2 ----
        {
            const float4* mc4 = (const float4*)smc;
            const float4* ms4 = (const float4*)sms;
            const float4* pr4 = (const float4*)sPr;
            const float4* pi4 = (const float4*)sPi;
            for (int w = tid; w < 256; w += T) {
                int kp = w >> 3, q = w & 7;
                int k10 = kp*2, k11 = k10+1;
                int row0 = (k10 <= 32) ? k10 : 63-k10; float sg0 = (k10 <= 32) ? 1.f : -1.f;
                int row1 = (k11 <= 32) ? k11 : 63-k11; float sg1 = (k11 <= 32) ? 1.f : -1.f;
                int k20 = q << 2;
                float ar0[4]={0,0,0,0}, ai0[4]={0,0,0,0}, ar1[4]={0,0,0,0}, ai1[4]={0,0,0,0};
                #pragma unroll 4
                for (int mc = 0; mc < 16; mc++) {
                    float4 c0 = mc4[row0*16 + mc];
                    float4 s0 = ms4[row0*16 + mc];
                    float4 c1 = mc4[row1*16 + mc];
                    float4 s1 = ms4[row1*16 + mc];
                    s0.x*=sg0; s0.y*=sg0; s0.z*=sg0; s0.w*=sg0;
                    s1.x*=sg1; s1.y*=sg1; s1.z*=sg1; s1.w*=sg1;
                    #pragma unroll
                    for (int kk = 0; kk < 4; kk++) {
                        float4 p = pr4[(k20+kk)*16 + mc];
                        float4 qi = pi4[(k20+kk)*16 + mc];
                        ar0[kk] += c0.x*p.x + c0.y*p.y + c0.z*p.z + c0.w*p.w
                                 + s0.x*qi.x + s0.y*qi.y + s0.z*qi.z + s0.w*qi.w;
                        ai0[kk] += c0.x*qi.x + c0.y*qi.y + c0.z*qi.z + c0.w*qi.w
                                 - s0.x*p.x - s0.y*p.y - s0.z*p.z - s0.w*p.w;
                        ar1[kk] += c1.x*p.x + c1.y*p.y + c1.z*p.z + c1.w*p.w
                                 + s1.x*qi.x + s1.y*qi.y + s1.z*qi.z + s1.w*qi.w;
                        ai1[kk] += c1.x*qi.x + c1.y*qi.y + c1.z*qi.z + c1.w*qi.w
                                 - s1.x*p.x - s1.y*p.y - s1.z*p.z - s1.w*p.w;
                    }
                }
                #pragma unroll
                for (int kk = 0; kk < 4; kk++) {
                    int e0 = k10*32 + k20 + kk;
                    float a = ar0[kk]*inv, bi = ai0[kk]*inv;
                    float wr = swcr[e0], wi = swci[e0];
                    sCr[e0] = a*wr - bi*wi;
                    sCi[e0] = a*wi + bi*wr;
                }
                if (k11 < 63) {
                    #pragma unroll
                    for (int kk = 0; kk < 4; kk++) {
                        int e1 = k11*32 + k20 + kk;
                        float a = ar1[kk]*inv, bi = ai1[kk]*inv;
                        float wr = swcr[e1], wi = swci[e1];
                        sCr[e1] = a*wr - bi*wi;
                        sCi[e1] = a*wi + bi*wr;
                    }
                }
            }
        }
        __syncthreads();

        // ---- (D) D[m][k2] = inv * sum_k1 W[m,k1] C[k1][k2] ; 2m x 4k2 ----
        {
            const float4* mc4 = (const float4*)smc;
            const float4* ms4 = (const float4*)sms;
            for (int w = tid; w < 256; w += T) {
                int mp = w >> 3, q = w & 7;
                int m0 = mp*2, m1 = m0+1;
                int row0 = (m0 <= 32) ? m0 : 63-m0; float sg0 = (m0 <= 32) ? 1.f : -1.f;
                int row1 = (m1 <= 32) ? m1 : 63-m1; float sg1 = (m1 <= 32) ? 1.f : -1.f;
                int k20 = q << 2;
                float dr0[4]={0,0,0,0}, di0[4]={0,0,0,0}, dr1[4]={0,0,0,0}, di1[4]={0,0,0,0};
                #pragma unroll 4
                for (int kc = 0; kc < 16; kc++) {
                    float4 c0 = mc4[row0*16 + kc];
                    float4 s0 = ms4[row0*16 + kc];
                    float4 c1 = mc4[row1*16 + kc];
                    float4 s1 = ms4[row1*16 + kc];
                    s0.x*=sg0; s0.y*=sg0; s0.z*=sg0; s0.w*=sg0;
                    s1.x*=sg1; s1.y*=sg1; s1.z*=sg1; s1.w*=sg1;
                    int k1 = kc << 2;
                    #pragma unroll
                    for (int kk = 0; kk < 4; kk++) {
                        float cr0 = sCr[(k1+0)*32 + k20+kk], ci0 = sCi[(k1+0)*32 + k20+kk];
                        float cr1 = sCr[(k1+1)*32 + k20+kk], ci1 = sCi[(k1+1)*32 + k20+kk];
                        float cr2 = sCr[(k1+2)*32 + k20+kk], ci2 = sCi[(k1+2)*32 + k20+kk];
                        float cr3 = sCr[(k1+3)*32 + k20+kk], ci3 = sCi[(k1+3)*32 + k20+kk];
                        dr0[kk] += c0.x*cr0 - s0.x*ci0 + c0.y*cr1 - s0.y*ci1
                                 + c0.z*cr2 - s0.z*ci2 + c0.w*cr3 - s0.w*ci3;
                        di0[kk] += c0.x*ci0 + s0.x*cr0 + c0.y*ci1 + s0.y*cr1
                                 + c0.z*ci2 + s0.z*cr2 + c0.w*ci3 + s0.w*cr3;
                        dr1[kk] += c1.x*cr0 - s1.x*ci0 + c1.y*cr1 - s1.y*ci1
                                 + c1.z*cr2 - s1.z*ci2 + c1.w*cr3 - s1.w*ci3;
                        di1[kk] += c1.x*ci0 + s1.x*cr0 + c1.y*ci1 + s1.y*cr1
                                 + c1.z*ci2 + s1.z*cr2 + c1.w*ci3 + s1.w*cr3;
                    }
                }
                #pragma unroll
                for (int kk = 0; kk < 4; kk++) {
                    sDr[m0*32 + k20+kk] = dr0[kk]*inv;
                    sDi[m0*32 + k20+kk] = di0[kk]*inv;
                }
                if (m1 < 63) {
                    #pragma unroll
                    for (int kk = 0; kk < 4; kk++) {
                        sDr[m1*32 + k20+kk] = dr1[kk]*inv;
                        sDi[m1*32 + k20+kk] = di1[kk]*inv;
                    }
                }
            }
        }
        __syncthreads();

        // ---- (h) x[m,n] += inv*(Dr[m,0] + 2*sum_{k2=1..31} Re(D[m,k2] W[k2,n])) ----
        {
            const float4* mc4 = (const float4*)smc;
            const float4* ms4 = (const float4*)sms;
            for (int w = tid; w < 512; w += T) {
                int mp = w >> 4, g = w & 15;
                int m0 = mp*2, m1 = m0+1;
                int n0 = g << 2;
                const float* d0r = sDr + m0*32;
                const float* d0i = sDi + m0*32;
                const float* d1r = sDr + m1*32;   // m1==63: row 63 exists? no: sDr is 2016=63*32
                const float* d1i = sDi + m1*32;
                bool do1 = (m1 < 63);
                float4 A0 = {0,0,0,0}, A1 = {0,0,0,0};
                #pragma unroll 8
                for (int k2 = 1; k2 < 32; k2++) {
                    float4 c = mc4[k2*16 + g];
                    float4 s = ms4[k2*16 + g];
                    float e0r = d0r[k2], e0i = d0i[k2];
                    A0.x += e0r*c.x - e0i*s.x;
                    A0.y += e0r*c.y - e0i*s.y;
                    A0.z += e0r*c.z - e0i*s.z;
                    A0.w += e0r*c.w - e0i*s.w;
                    if (do1) {
                        float e1r = d1r[k2], e1i = d1i[k2];
                        A1.x += e1r*c.x - e1i*s.x;
                        A1.y += e1r*c.y - e1i*s.y;
                        A1.z += e1r*c.z - e1i*s.z;
                        A1.w += e1r*c.w - e1i*s.w;
                    }
                }
                float base0 = d0r[0];
                float* xo0 = sxp + (m0+1)*68 + n0 + 1;
                xo0[0] += (base0 + 2.f*A0.x)*inv;
                xo0[1] += (base0 + 2.f*A0.y)*inv;
                xo0[2] += (base0 + 2.f*A0.z)*inv;
                if (g < 15) xo0[3] += (base0 + 2.f*A0.w)*inv;
                if (do1) {
                    float base1 = d1r[0];
                    float* xo1 = sxp + (m1+1)*68 + n0 + 1;
                    xo1[0] += (base1 + 2.f*A1.x)*inv;
                    xo1[1] += (base1 + 2.f*A1.y)*inv;
                    xo1[2] += (base1 + 2.f*A1.z)*inv;
                    if (g < 15) xo1[3] += (base1 + 2.f*A1.w)*inv;
                }
            }
        }
        __syncthreads();
    }

    // ---- final residual + sum of squares ----
    float loc = 0.f;
    #pragma unroll
    for (int p = 0; p < 8; p++) {
        int el = tid + p*T;
        if (el >= NP64) break;
        int i = el >> 6, j = el & 63;
        if (j >= 63) continue;
        const float* xb = sxp + i*68 + j;
        float acc = ska[0]*xb[0] + ska[1]*xb[1] + ska[2]*xb[2]
                  + ska[3]*xb[68] + ska[4]*xb[69] + ska[5]*xb[70]
                  + ska[6]*xb[136] + ska[7]*xb[137] + ska[8]*xb[138];
        float v = fr[p] - acc;
        loc += v * v;
    }
    #pragma unroll
    for (int off = 16; off; off >>= 1)
        loc += __shfl_xor_sync(0xFFFFFFFFu, loc, off);
    __shared__ float wsum[16];
    int wid = tid >> 5;
    if ((tid & 31) == 0) wsum[wid] = loc;
    __syncthreads();
    if (tid == 0) {
        float s = 0.f;
        #pragma unroll
        for (int w = 0; w < 16; w++) s += wsum[w];
        g_blocksum[b] = s;
    }
}

__global__ void final_reduce_kernel(float* __restrict__ out) {
    __shared__ float s[BATCH];
    s[threadIdx.x] = g_blocksum[threadIdx.x];
    __syncthreads();
    for (int st = BATCH/2; st > 0; st >>= 1) {
        if (threadIdx.x < st) s[threadIdx.x] += s[threadIdx.x + st];
        __syncthreads();
    }
    if (threadIdx.x == 0) out[0] = sqrtf(s[0]) / 256.0f;
}

// ---------------- host ----------------
extern "C" void kernel_launch(void* const* d_in, const int* in_sizes, int n_in,
                              void* d_out, int out_size) {
    const float* x      = (const float*)d_in[0];
    const float* f      = (const float*)d_in[1];
    const float* kA     = (const float*)d_in[2];
    const float* fc1_w1 = (const float*)d_in[3];
    const float* fc1_b1 = (const float*)d_in[4];
    const float* fc1_w2 = (const float*)d_in[5];
    const float* fc1_b2 = (const float*)d_in[6];
    const float* fc2_w1 = (const float*)d_in[7];
    const float* fc2_b1 = (const float*)d_in[8];
    const float* fc2_w2 = (const float*)d_in[9];
    const float* fc2_b2 = (const float*)d_in[10];
    const float* ct1_w  = (const float*)d_in[11];
    const float* ct1_b  = (const float*)d_in[12];
    const float* ct2_w  = (const float*)d_in[13];
    const float* ct2_b  = (const float*)d_in[14];
    const float* ct3_w  = (const float*)d_in[15];
    const float* ct3_b  = (const float*)d_in[16];
    const float* ct4_w  = (const float*)d_in[17];
    const float* ct4_b  = (const float*)d_in[18];
    const float* ct5_w  = (const float*)d_in[19];
    const float* ct5_b  = (const float*)d_in[20];
    float* out = (float*)d_out;

    cudaFuncSetAttribute(solver_kernel, cudaFuncAttributeMaxDynamicSharedMemorySize,
                         SMEM_FLOATS * (int)sizeof(float));

    init_tw_kernel<<<(33*64 + 255)/256, 256>>>();
    hyper_kernel<<<BATCH, 256>>>(kA, fc1_w1, fc1_b1, fc1_w2, fc1_b2,
                                 fc2_w1, fc2_b1, fc2_w2, fc2_b2);
    ct1_kernel<<<BATCH, 256>>>(kA, ct1_w, ct1_b);
    ct_mid_kernel<5> <<<dim3(BATCH, 4), 256>>>(g_a1, ct2_w, ct2_b, g_a2);
    ct_mid_kernel<9> <<<dim3(BATCH, 4), 256>>>(g_a2, ct3_w, ct3_b, g_a3);
    ct_mid_kernel<17><<<dim3(BATCH, 4), 256>>>(g_a3, ct4_w, ct4_b, g_a4);
    ct5_kernel<<<BATCH, 256>>>(ct5_w, ct5_b);
    solver_kernel<<<BATCH, 512, SMEM_FLOATS * sizeof(float)>>>(x, f, kA);
    final_reduce_kernel<<<1, BATCH>>>(out);
}